// round 8
// baseline (speedup 1.0000x reference)
#include <cuda_runtime.h>
#include <cuda_fp16.h>
#include <cstdint>

#define MAX_N 100352
#define MAX_E 1700000
#define DIM 128

// ---------------- small device-global scratch (~8.4 MB total) ----------------
__device__ int   g_deg[MAX_N];        // degree, then reused as CSR fill cursor
__device__ float g_dinv[MAX_N];
__device__ float g_invcnt[MAX_N];
__device__ int   g_row[MAX_N + 1];    // CSR row pointers (by dst)
__device__ int   g_col[MAX_E];        // CSR: src node per slot
__device__ int   g_idx64;             // 1 if edge index is int64

// ---------------- edge-index dtype detection ----------------
// int64 ids < 2^31 -> every odd 32-bit word is zero. words==0 writes nothing.
__global__ void detect_kernel(const int* ei32, long long words) {
    __shared__ int s;
    if (threadIdx.x == 0) s = 1;
    __syncthreads();
    long long limit = words < 8192 ? words : 8192;
    for (long long j = 1 + 2LL * threadIdx.x; j < limit; j += 2LL * blockDim.x)
        if (ei32[j] != 0) s = 0;
    __syncthreads();
    if (threadIdx.x == 0 && words > 0) g_idx64 = s;
}

__device__ __forceinline__ void load_edge(const void* ei, long long E, long long e,
                                          int& src, int& dst) {
    if (g_idx64) {
        const long long* p = (const long long*)ei;
        src = (int)p[e]; dst = (int)p[E + e];
    } else {
        const int* p = (const int*)ei;
        src = p[e]; dst = p[E + e];
    }
}

// ---------------- degree / norm precompute ----------------
__global__ void zero_deg_kernel(int n) {
    int i = blockIdx.x * blockDim.x + threadIdx.x;
    if (i < n) g_deg[i] = 0;
}

__global__ void count_deg_kernel(const void* ei, long long E) {
    long long e = (long long)blockIdx.x * blockDim.x + threadIdx.x;
    if (e < E) {
        int s, d; load_edge(ei, E, e, s, d);
        atomicAdd(&g_deg[d], 1);
    }
}

__global__ void precompute_kernel(int n) {
    int i = blockIdx.x * blockDim.x + threadIdx.x;
    if (i < n) {
        int d = g_deg[i];
        g_dinv[i]   = rsqrtf((float)d + 1.0f);        // GCN self-loop degree
        g_invcnt[i] = 1.0f / (float)(d > 0 ? d : 1);  // SAGE mean denom
    }
}

// ---------------- exclusive scan (single block): row_ptr; deg becomes cursor ----------------
__global__ __launch_bounds__(1024) void scan_kernel(int n) {
    __shared__ int sums[1024];
    const int t = threadIdx.x;
    const int chunk = (n + 1023) / 1024;
    const int lo = t * chunk;
    const int hi = min(lo + chunk, n);
    int s = 0;
    for (int i = lo; i < hi; i++) s += g_deg[i];
    sums[t] = s;
    __syncthreads();
    for (int d = 1; d < 1024; d <<= 1) {
        int u = (t >= d) ? sums[t - d] : 0;
        __syncthreads();
        sums[t] += u;
        __syncthreads();
    }
    int run = sums[t] - s;   // exclusive prefix for this chunk
    for (int i = lo; i < hi; i++) {
        int d = g_deg[i];
        g_row[i] = run;
        g_deg[i] = run;      // cursor init (safe: read-then-write per element)
        run += d;
    }
    if (t == 1023) g_row[n] = run;
}

__global__ void fill_kernel(const void* ei, long long E) {
    long long e = (long long)blockIdx.x * blockDim.x + threadIdx.x;
    if (e < E) {
        int s, d; load_edge(ei, E, e, s, d);
        int pos = atomicAdd(&g_deg[d], 1);
        g_col[pos] = s;
    }
}

// ---------------- L1 aggregate (aggregation-first GCN): agg -> d_out fp32 ----------------
// warp per node; lane covers 4 feature dims (float4).
__global__ __launch_bounds__(256) void agg1_kernel(
    const float* __restrict__ feat, float* __restrict__ out, int n)
{
    int node = blockIdx.x * 8 + (threadIdx.x >> 5);
    if (node >= n) return;
    const int lane = threadIdx.x & 31;
    const float di = g_dinv[node];

    float4 f = *(const float4*)&feat[(size_t)node * DIM + lane * 4];
    float c0 = di * di;
    float4 acc = make_float4(c0 * f.x, c0 * f.y, c0 * f.z, c0 * f.w);

    const int pend = g_row[node + 1];
    for (int p = g_row[node]; p < pend; p++) {
        int j = g_col[p];
        float c = di * g_dinv[j];
        float4 v = *(const float4*)&feat[(size_t)j * DIM + lane * 4];
        acc.x += c * v.x; acc.y += c * v.y; acc.z += c * v.z; acc.w += c * v.w;
    }
    *(float4*)&out[(size_t)node * DIM + lane * 4] = acc;
}

// ---------------- GEMM1 in place: X = relu(agg@W1^T + b1) -> fp16 in slot[0:256B) ----------------
__global__ __launch_bounds__(256) void gemm1_kernel(
    const float* __restrict__ W1, const float* __restrict__ b1,
    float* __restrict__ out, int n)
{
    extern __shared__ float sm[];
    float* Wt = sm;                  // [128][132]
    float* As = sm + 128 * 132;      // [64][128]
    const int tid = threadIdx.x;
    const int block_row = blockIdx.x * 64;

    for (int i = tid; i < 128 * 128; i += 256) {
        int c = i >> 7, k = i & 127;
        Wt[k * 132 + c] = W1[i];
    }
    for (int i = tid; i < 64 * 128; i += 256) {
        int r = i >> 7, k = i & 127;
        int gr = block_row + r;
        As[r * 128 + k] = (gr < n) ? out[(size_t)gr * DIM + k] : 0.f;
    }
    __syncthreads();

    const int cg = tid & 31, rg = tid >> 5;
    const int c0 = cg * 4, r0 = rg * 8;
    float acc[8][4];
    #pragma unroll
    for (int j = 0; j < 8; j++)
        #pragma unroll
        for (int q = 0; q < 4; q++) acc[j][q] = 0.f;

    #pragma unroll 2
    for (int k = 0; k < 128; k += 4) {
        float4 w0 = *(float4*)&Wt[(k + 0) * 132 + c0];
        float4 w1 = *(float4*)&Wt[(k + 1) * 132 + c0];
        float4 w2 = *(float4*)&Wt[(k + 2) * 132 + c0];
        float4 w3 = *(float4*)&Wt[(k + 3) * 132 + c0];
        #pragma unroll
        for (int j = 0; j < 8; j++) {
            float4 a = *(float4*)&As[(r0 + j) * 128 + k];
            acc[j][0] += a.x * w0.x + a.y * w1.x + a.z * w2.x + a.w * w3.x;
            acc[j][1] += a.x * w0.y + a.y * w1.y + a.z * w2.y + a.w * w3.y;
            acc[j][2] += a.x * w0.z + a.y * w1.z + a.z * w2.z + a.w * w3.z;
            acc[j][3] += a.x * w0.w + a.y * w1.w + a.z * w2.w + a.w * w3.w;
        }
    }

    float4 bv = *(const float4*)&b1[c0];
    #pragma unroll
    for (int j = 0; j < 8; j++) {
        int gr = block_row + r0 + j;
        if (gr < n) {
            float x0 = fmaxf(acc[j][0] + bv.x, 0.f);
            float x1 = fmaxf(acc[j][1] + bv.y, 0.f);
            float x2 = fmaxf(acc[j][2] + bv.z, 0.f);
            float x3 = fmaxf(acc[j][3] + bv.w, 0.f);
            __half2* xh = (__half2*)((__half*)(out + (size_t)gr * DIM) + c0);
            xh[0] = __floats2half2_rn(x0, x1);
            xh[1] = __floats2half2_rn(x2, x3);
        }
    }
}

// ---------------- SAGE sum: S_i = sum_j X_j (fp32 acc) -> fp16 in slot[256:512B) ----------------
// warp per node; lane covers 4 halves (8 bytes). Reads X halves (slot low),
// writes S halves (slot high) — globally disjoint byte ranges, race-free.
__global__ __launch_bounds__(256) void sgather_kernel(float* __restrict__ out, int n) {
    int node = blockIdx.x * 8 + (threadIdx.x >> 5);
    if (node >= n) return;
    const int lane = threadIdx.x & 31;

    float4 acc = make_float4(0.f, 0.f, 0.f, 0.f);
    const int pend = g_row[node + 1];
    for (int p = g_row[node]; p < pend; p++) {
        int j = g_col[p];
        const __half2* xr = (const __half2*)((const __half*)(out + (size_t)j * DIM)) + lane * 2;
        float2 a = __half22float2(xr[0]);
        float2 b = __half22float2(xr[1]);
        acc.x += a.x; acc.y += a.y; acc.z += b.x; acc.w += b.y;
    }
    __half2* sh = (__half2*)((__half*)(out + (size_t)node * DIM + 64)) + lane * 2;
    sh[0] = __floats2half2_rn(acc.x, acc.y);
    sh[1] = __floats2half2_rn(acc.z, acc.w);
}

// ---------------- GEMM2 in place: out = relu([S*invcnt | X] @ [Wl|Wr]^T + bl) ----------------
__global__ __launch_bounds__(256) void gemm2_kernel(
    const float* __restrict__ Wl, const float* __restrict__ bl,
    const float* __restrict__ Wr, float* __restrict__ out, int n)
{
    extern __shared__ float sm[];
    float* Wt = sm;                  // [256][132]
    float* As = sm + 256 * 132;      // [64][256]
    const int tid = threadIdx.x;
    const int block_row = blockIdx.x * 64;

    for (int i = tid; i < 128 * 256; i += 256) {
        int c = i >> 8, k = i & 255;
        float w = (k < 128) ? Wl[c * 128 + k] : Wr[c * 128 + (k - 128)];
        Wt[k * 132 + c] = w;
    }
    for (int i = tid; i < 64 * 256; i += 256) {
        int r = i >> 8, k = i & 255;
        int gr = block_row + r;
        float v = 0.f;
        if (gr < n) {
            if (k < 128) {
                const __half* sh = (const __half*)(out + (size_t)gr * DIM + 64);
                v = __half2float(sh[k]) * g_invcnt[gr];
            } else {
                const __half* xh = (const __half*)(out + (size_t)gr * DIM);
                v = __half2float(xh[k - 128]);
            }
        }
        As[r * 256 + k] = v;
    }
    __syncthreads();

    const int cg = tid & 31, rg = tid >> 5;
    const int c0 = cg * 4, r0 = rg * 8;
    float acc[8][4];
    #pragma unroll
    for (int j = 0; j < 8; j++)
        #pragma unroll
        for (int q = 0; q < 4; q++) acc[j][q] = 0.f;

    #pragma unroll 2
    for (int k = 0; k < 256; k += 4) {
        float4 w0 = *(float4*)&Wt[(k + 0) * 132 + c0];
        float4 w1 = *(float4*)&Wt[(k + 1) * 132 + c0];
        float4 w2 = *(float4*)&Wt[(k + 2) * 132 + c0];
        float4 w3 = *(float4*)&Wt[(k + 3) * 132 + c0];
        #pragma unroll
        for (int j = 0; j < 8; j++) {
            float4 a = *(float4*)&As[(r0 + j) * 256 + k];
            acc[j][0] += a.x * w0.x + a.y * w1.x + a.z * w2.x + a.w * w3.x;
            acc[j][1] += a.x * w0.y + a.y * w1.y + a.z * w2.y + a.w * w3.y;
            acc[j][2] += a.x * w0.z + a.y * w1.z + a.z * w2.z + a.w * w3.z;
            acc[j][3] += a.x * w0.w + a.y * w1.w + a.z * w2.w + a.w * w3.w;
        }
    }

    float4 bv = *(const float4*)&bl[c0];
    #pragma unroll
    for (int j = 0; j < 8; j++) {
        int gr = block_row + r0 + j;
        if (gr < n) {
            float4 o = make_float4(fmaxf(acc[j][0] + bv.x, 0.f),
                                   fmaxf(acc[j][1] + bv.y, 0.f),
                                   fmaxf(acc[j][2] + bv.z, 0.f),
                                   fmaxf(acc[j][3] + bv.w, 0.f));
            *(float4*)&out[(size_t)gr * DIM + c0] = o;
        }
    }
}

static const int SMEM1 = (128 * 132 + 64 * 128) * 4;   // ~100 KB
static const int SMEM2 = (256 * 132 + 64 * 256) * 4;   // ~201 KB

// ---------------- host launcher ----------------
extern "C" void kernel_launch(void* const* d_in, const int* in_sizes, int n_in,
                              void* d_out, int out_size) {
    const float* feat = (const float*)d_in[0];
    const void*  ei   = d_in[1];
    const float* W1   = (const float*)d_in[2];
    const float* b1   = (const float*)d_in[3];
    const float* Wl   = (const float*)d_in[4];
    const float* bl   = (const float*)d_in[5];
    const float* Wr   = (const float*)d_in[6];
    float* out = (float*)d_out;

    const int n = in_sizes[0] / DIM;
    const long long E = (long long)in_sizes[1] / 2;

    static bool attr_done = false;
    if (!attr_done) {
        cudaFuncSetAttribute(gemm1_kernel, cudaFuncAttributeMaxDynamicSharedMemorySize, SMEM1);
        cudaFuncSetAttribute(gemm2_kernel, cudaFuncAttributeMaxDynamicSharedMemorySize, SMEM2);
        attr_done = true;
    }

    const int eb = (int)((E + 255) / 256);
    const int nb = (n + 255) / 256;
    const int wb = (n + 7) / 8;          // warp-per-node kernels
    const int gb = (n + 63) / 64;        // GEMM row blocks

    // 0. edge dtype
    detect_kernel<<<1, 256>>>((const int*)ei, 2 * E);
    // 1. degrees + norms
    zero_deg_kernel<<<nb, 256>>>(n);
    count_deg_kernel<<<eb, 256>>>(ei, E);
    precompute_kernel<<<nb, 256>>>(n);
    // 2. CSR build (row_ptr; deg -> cursor; col = src sorted by dst)
    scan_kernel<<<1, 1024>>>(n);
    fill_kernel<<<eb, 256>>>(ei, E);
    // 3. layer-1: aggregate-first GCN -> d_out fp32
    agg1_kernel<<<wb, 256>>>(feat, out, n);
    // 4. X = relu(agg@W1^T+b1) -> fp16, slot low half (in place, block-local)
    gemm1_kernel<<<gb, 256, SMEM1>>>(W1, b1, out, n);
    // 5. S_i = sum X_j -> fp16, slot high half
    sgather_kernel<<<wb, 256>>>(out, n);
    // 6. out = relu([S*invcnt | X] @ [Wl|Wr]^T + bl) -> fp32 (in place, block-local)
    gemm2_kernel<<<gb, 256, SMEM2>>>(Wl, bl, Wr, out, n);
}

// round 9
// speedup vs baseline: 2.8135x; 2.8135x over previous
#include <cuda_runtime.h>
#include <cuda_fp16.h>
#include <cstdint>

#define MAX_N 100352
#define MAX_E 1700000
#define MAX_PART 512
#define DIM 128

// ---------------- small device-global scratch (~8.4 MB total) ----------------
__device__ int   g_deg[MAX_N];        // degree, then CSR fill cursor
__device__ float g_dinv[MAX_N];
__device__ float g_invcnt[MAX_N];
__device__ int   g_row[MAX_N + 1];    // CSR row pointers (by dst)
__device__ int   g_col[MAX_E];        // CSR: src node per slot
__device__ int   g_part[MAX_PART];    // scan partials
__device__ int   g_idx64;             // 1 if edge index is int64

// ---------------- edge-index dtype detection ----------------
__global__ void detect_kernel(const int* ei32, long long words) {
    __shared__ int s;
    if (threadIdx.x == 0) s = 1;
    __syncthreads();
    long long limit = words < 8192 ? words : 8192;
    for (long long j = 1 + 2LL * threadIdx.x; j < limit; j += 2LL * blockDim.x)
        if (ei32[j] != 0) s = 0;
    __syncthreads();
    if (threadIdx.x == 0 && words > 0) g_idx64 = s;
}

__device__ __forceinline__ void load_edge(const void* ei, long long E, long long e,
                                          int& src, int& dst) {
    if (g_idx64) {
        const long long* p = (const long long*)ei;
        src = (int)p[e]; dst = (int)p[E + e];
    } else {
        const int* p = (const int*)ei;
        src = p[e]; dst = p[E + e];
    }
}

// ---------------- degree / norm precompute ----------------
__global__ void zero_deg_kernel(int n) {
    int i = blockIdx.x * blockDim.x + threadIdx.x;
    if (i < n) g_deg[i] = 0;
}

__global__ void count_deg_kernel(const void* ei, long long E) {
    long long e = (long long)blockIdx.x * blockDim.x + threadIdx.x;
    if (e < E) {
        int s, d; load_edge(ei, E, e, s, d);
        atomicAdd(&g_deg[d], 1);
    }
}

__global__ void precompute_kernel(int n) {
    int i = blockIdx.x * blockDim.x + threadIdx.x;
    if (i < n) {
        int d = g_deg[i];
        g_dinv[i]   = rsqrtf((float)d + 1.0f);
        g_invcnt[i] = 1.0f / (float)(d > 0 ? d : 1);
    }
}

// ---------------- 3-kernel exclusive scan -> row_ptr + cursor ----------------
__global__ __launch_bounds__(256) void partial_kernel(int n) {
    __shared__ int red[256];
    int i = blockIdx.x * 256 + threadIdx.x;
    red[threadIdx.x] = (i < n) ? g_deg[i] : 0;
    __syncthreads();
    for (int s = 128; s > 0; s >>= 1) {
        if (threadIdx.x < s) red[threadIdx.x] += red[threadIdx.x + s];
        __syncthreads();
    }
    if (threadIdx.x == 0) g_part[blockIdx.x] = red[0];
}

__global__ __launch_bounds__(512) void scan_part_kernel(int nb, int n) {
    __shared__ int sp[512];
    int t = threadIdx.x;
    int v = (t < nb) ? g_part[t] : 0;
    sp[t] = v;
    __syncthreads();
    for (int d = 1; d < 512; d <<= 1) {
        int u = (t >= d) ? sp[t - d] : 0;
        __syncthreads();
        sp[t] += u;
        __syncthreads();
    }
    if (t < nb) g_part[t] = sp[t] - v;       // exclusive
    if (t == 511) g_row[n] = sp[511];        // total
}

__global__ __launch_bounds__(256) void rowptr_kernel(int n) {
    __shared__ int sp[256];
    int t = threadIdx.x;
    int i = blockIdx.x * 256 + t;
    int v = (i < n) ? g_deg[i] : 0;
    sp[t] = v;
    __syncthreads();
    for (int d = 1; d < 256; d <<= 1) {
        int u = (t >= d) ? sp[t - d] : 0;
        __syncthreads();
        sp[t] += u;
        __syncthreads();
    }
    int excl = sp[t] - v + g_part[blockIdx.x];
    if (i < n) { g_row[i] = excl; g_deg[i] = excl; }
}

__global__ void fill_kernel(const void* ei, long long E) {
    long long e = (long long)blockIdx.x * blockDim.x + threadIdx.x;
    if (e < E) {
        int s, d; load_edge(ei, E, e, s, d);
        int pos = atomicAdd(&g_deg[d], 1);
        g_col[pos] = s;
    }
}

// ---------------- L1 aggregate (aggregation-first GCN) -> d_out fp32 ----------------
__global__ __launch_bounds__(256) void agg1_kernel(
    const float* __restrict__ feat, float* __restrict__ out, int n)
{
    int node = blockIdx.x * 8 + (threadIdx.x >> 5);
    if (node >= n) return;
    const int lane = threadIdx.x & 31;
    const float di = g_dinv[node];

    float4 f = *(const float4*)&feat[(size_t)node * DIM + lane * 4];
    float c0 = di * di;
    float4 acc = make_float4(c0 * f.x, c0 * f.y, c0 * f.z, c0 * f.w);

    const int pend = g_row[node + 1];
    for (int p = g_row[node]; p < pend; p++) {
        int j = g_col[p];
        float c = di * g_dinv[j];
        float4 v = *(const float4*)&feat[(size_t)j * DIM + lane * 4];
        acc.x += c * v.x; acc.y += c * v.y; acc.z += c * v.z; acc.w += c * v.w;
    }
    *(float4*)&out[(size_t)node * DIM + lane * 4] = acc;
}

// ---------------- tensor-core mma helper ----------------
__device__ __forceinline__ void mma16816(float* c, uint32_t a0, uint32_t a1,
                                         uint32_t a2, uint32_t a3,
                                         uint32_t b0, uint32_t b1) {
    asm volatile(
        "mma.sync.aligned.m16n8k16.row.col.f32.f16.f16.f32 "
        "{%0,%1,%2,%3}, {%4,%5,%6,%7}, {%8,%9}, {%0,%1,%2,%3};"
        : "+f"(c[0]), "+f"(c[1]), "+f"(c[2]), "+f"(c[3])
        : "r"(a0), "r"(a1), "r"(a2), "r"(a3), "r"(b0), "r"(b1));
}

// ---------------- GEMM1 (tensor core): X = relu(agg@W1^T + b1) -> fp16 slot low ----------------
// block: 256 thr (8 warps), tile 128 rows x 128 cols, K=128 resident in smem.
__global__ __launch_bounds__(256) void mma_gemm1(
    const float* __restrict__ W1, const float* __restrict__ b1,
    float* __restrict__ out, int n)
{
    const int KP = 136;                       // K + 8 halves pad -> conflict-free
    extern __shared__ __half sh[];
    __half* As = sh;                          // [128][136]
    __half* Bs = sh + 128 * KP;               // [128][136]
    float* bias_s = (float*)(Bs + 128 * KP);  // [128]
    const int tid = threadIdx.x;
    const int block_row = blockIdx.x * 128;

    // B = W1 (fp32 [128][128]) -> fp16
    for (int i = tid; i < 128 * 32; i += 256) {
        int r = i >> 5, q = i & 31;
        float4 w = ((const float4*)W1)[i];
        __half2* dst = (__half2*)&Bs[r * KP + q * 4];
        dst[0] = __floats2half2_rn(w.x, w.y);
        dst[1] = __floats2half2_rn(w.z, w.w);
    }
    // A = agg rows (fp32 in d_out) -> fp16
    for (int i = tid; i < 128 * 32; i += 256) {
        int r = i >> 5, q = i & 31;
        int gr = block_row + r;
        float4 v = (gr < n) ? ((const float4*)(out + (size_t)gr * DIM))[q]
                            : make_float4(0.f, 0.f, 0.f, 0.f);
        __half2* dst = (__half2*)&As[r * KP + q * 4];
        dst[0] = __floats2half2_rn(v.x, v.y);
        dst[1] = __floats2half2_rn(v.z, v.w);
    }
    if (tid < 128) bias_s[tid] = b1[tid];
    __syncthreads();

    const int warp = tid >> 5, lane = tid & 31;
    const int m0 = warp * 16;
    const int r = lane >> 2, c2 = (lane & 3) * 2;

    float acc[16][4];
    #pragma unroll
    for (int t = 0; t < 16; t++)
        #pragma unroll
        for (int q = 0; q < 4; q++) acc[t][q] = 0.f;

    #pragma unroll
    for (int kk = 0; kk < 128; kk += 16) {
        uint32_t a0 = *(const uint32_t*)&As[(m0 + r) * KP + kk + c2];
        uint32_t a1 = *(const uint32_t*)&As[(m0 + r + 8) * KP + kk + c2];
        uint32_t a2 = *(const uint32_t*)&As[(m0 + r) * KP + kk + 8 + c2];
        uint32_t a3 = *(const uint32_t*)&As[(m0 + r + 8) * KP + kk + 8 + c2];
        #pragma unroll
        for (int nt = 0; nt < 16; nt++) {
            uint32_t b0 = *(const uint32_t*)&Bs[(nt * 8 + r) * KP + kk + c2];
            uint32_t b1r = *(const uint32_t*)&Bs[(nt * 8 + r) * KP + kk + 8 + c2];
            mma16816(acc[nt], a0, a1, a2, a3, b0, b1r);
        }
    }

    const int row0 = block_row + m0 + r;
    #pragma unroll
    for (int nt = 0; nt < 16; nt++) {
        int col = nt * 8 + c2;
        float bx = bias_s[col], by = bias_s[col + 1];
        if (row0 < n) {
            __half2 h = __floats2half2_rn(fmaxf(acc[nt][0] + bx, 0.f),
                                          fmaxf(acc[nt][1] + by, 0.f));
            *(__half2*)((__half*)(out + (size_t)row0 * DIM) + col) = h;
        }
        if (row0 + 8 < n) {
            __half2 h = __floats2half2_rn(fmaxf(acc[nt][2] + bx, 0.f),
                                          fmaxf(acc[nt][3] + by, 0.f));
            *(__half2*)((__half*)(out + (size_t)(row0 + 8) * DIM) + col) = h;
        }
    }
}

// ---------------- SAGE sum: S_i = sum_j X_j (fp32 acc) -> fp16 slot high ----------------
__global__ __launch_bounds__(256) void sgather_kernel(float* __restrict__ out, int n) {
    int node = blockIdx.x * 8 + (threadIdx.x >> 5);
    if (node >= n) return;
    const int lane = threadIdx.x & 31;

    float4 acc = make_float4(0.f, 0.f, 0.f, 0.f);
    const int pend = g_row[node + 1];
    for (int p = g_row[node]; p < pend; p++) {
        int j = g_col[p];
        const __half2* xr = (const __half2*)((const __half*)(out + (size_t)j * DIM)) + lane * 2;
        float2 a = __half22float2(xr[0]);
        float2 b = __half22float2(xr[1]);
        acc.x += a.x; acc.y += a.y; acc.z += b.x; acc.w += b.y;
    }
    __half2* shp = (__half2*)((__half*)(out + (size_t)node * DIM + 64)) + lane * 2;
    shp[0] = __floats2half2_rn(acc.x, acc.y);
    shp[1] = __floats2half2_rn(acc.z, acc.w);
}

// ---------------- GEMM2 (tensor core): out = relu([S*invcnt | X] @ [Wl|Wr]^T + bl) ----------------
// K=256 resident in smem; in-place block-local (reads own slots, writes fp32 rows).
__global__ __launch_bounds__(256) void mma_gemm2(
    const float* __restrict__ Wl, const float* __restrict__ bl,
    const float* __restrict__ Wr, float* __restrict__ out, int n)
{
    const int KP = 264;                       // 256 + 8 halves pad
    extern __shared__ __half sh[];
    __half* As = sh;                          // [128][264]
    __half* Bs = sh + 128 * KP;               // [128][264]
    float* bias_s = (float*)(Bs + 128 * KP);  // [128]
    const int tid = threadIdx.x;
    const int block_row = blockIdx.x * 128;

    // B: cols [0:128)=Wl, [128:256)=Wr  (fp32 -> fp16)
    for (int i = tid; i < 128 * 32; i += 256) {
        int r = i >> 5, q = i & 31;
        float4 w = ((const float4*)Wl)[i];
        __half2* dst = (__half2*)&Bs[r * KP + q * 4];
        dst[0] = __floats2half2_rn(w.x, w.y);
        dst[1] = __floats2half2_rn(w.z, w.w);
    }
    for (int i = tid; i < 128 * 32; i += 256) {
        int r = i >> 5, q = i & 31;
        float4 w = ((const float4*)Wr)[i];
        __half2* dst = (__half2*)&Bs[r * KP + 128 + q * 4];
        dst[0] = __floats2half2_rn(w.x, w.y);
        dst[1] = __floats2half2_rn(w.z, w.w);
    }
    // A: cols [0:128) = S*invcnt (slot high halves), [128:256) = X (slot low halves)
    for (int i = tid; i < 128 * 64; i += 256) {
        int row = i >> 6, q = i & 63;          // q: half2 index 0..63
        int gr = block_row + row;
        __half2 xh = __float2half2_rn(0.f), shv = __float2half2_rn(0.f);
        if (gr < n) {
            const __half2* slot = (const __half2*)(out + (size_t)gr * DIM);
            xh = slot[q];                      // X halves 0..127
            __half2 sr = slot[64 + q];         // S halves 128..255
            float ic = g_invcnt[gr];
            float2 sf = __half22float2(sr);
            shv = __floats2half2_rn(sf.x * ic, sf.y * ic);
        }
        ((__half2*)&As[row * KP])[q] = shv;
        ((__half2*)&As[row * KP + 128])[q] = xh;
    }
    if (tid < 128) bias_s[tid] = bl[tid];
    __syncthreads();

    const int warp = tid >> 5, lane = tid & 31;
    const int m0 = warp * 16;
    const int r = lane >> 2, c2 = (lane & 3) * 2;

    float acc[16][4];
    #pragma unroll
    for (int t = 0; t < 16; t++)
        #pragma unroll
        for (int q = 0; q < 4; q++) acc[t][q] = 0.f;

    #pragma unroll
    for (int kk = 0; kk < 256; kk += 16) {
        uint32_t a0 = *(const uint32_t*)&As[(m0 + r) * KP + kk + c2];
        uint32_t a1 = *(const uint32_t*)&As[(m0 + r + 8) * KP + kk + c2];
        uint32_t a2 = *(const uint32_t*)&As[(m0 + r) * KP + kk + 8 + c2];
        uint32_t a3 = *(const uint32_t*)&As[(m0 + r + 8) * KP + kk + 8 + c2];
        #pragma unroll
        for (int nt = 0; nt < 16; nt++) {
            uint32_t b0 = *(const uint32_t*)&Bs[(nt * 8 + r) * KP + kk + c2];
            uint32_t b1r = *(const uint32_t*)&Bs[(nt * 8 + r) * KP + kk + 8 + c2];
            mma16816(acc[nt], a0, a1, a2, a3, b0, b1r);
        }
    }

    const int row0 = block_row + m0 + r;
    #pragma unroll
    for (int nt = 0; nt < 16; nt++) {
        int col = nt * 8 + c2;
        float bx = bias_s[col], by = bias_s[col + 1];
        if (row0 < n) {
            float2 o = make_float2(fmaxf(acc[nt][0] + bx, 0.f),
                                   fmaxf(acc[nt][1] + by, 0.f));
            *(float2*)(out + (size_t)row0 * DIM + col) = o;
        }
        if (row0 + 8 < n) {
            float2 o = make_float2(fmaxf(acc[nt][2] + bx, 0.f),
                                   fmaxf(acc[nt][3] + by, 0.f));
            *(float2*)(out + (size_t)(row0 + 8) * DIM + col) = o;
        }
    }
}

static const int SMEM_G1 = (128 * 136 * 2) * 2 + 512;   // ~70 KB
static const int SMEM_G2 = (128 * 264 * 2) * 2 + 512;   // ~136 KB

// ---------------- host launcher ----------------
extern "C" void kernel_launch(void* const* d_in, const int* in_sizes, int n_in,
                              void* d_out, int out_size) {
    const float* feat = (const float*)d_in[0];
    const void*  ei   = d_in[1];
    const float* W1   = (const float*)d_in[2];
    const float* b1   = (const float*)d_in[3];
    const float* Wl   = (const float*)d_in[4];
    const float* bl   = (const float*)d_in[5];
    const float* Wr   = (const float*)d_in[6];
    float* out = (float*)d_out;

    const int n = in_sizes[0] / DIM;
    const long long E = (long long)in_sizes[1] / 2;

    static bool attr_done = false;
    if (!attr_done) {
        cudaFuncSetAttribute(mma_gemm1, cudaFuncAttributeMaxDynamicSharedMemorySize, SMEM_G1);
        cudaFuncSetAttribute(mma_gemm2, cudaFuncAttributeMaxDynamicSharedMemorySize, SMEM_G2);
        attr_done = true;
    }

    const int eb = (int)((E + 255) / 256);
    const int nb = (n + 255) / 256;          // also scan partial count
    const int wb = (n + 7) / 8;              // warp-per-node kernels
    const int mb = (n + 127) / 128;          // mma GEMM row blocks

    detect_kernel<<<1, 256>>>((const int*)ei, 2 * E);
    zero_deg_kernel<<<nb, 256>>>(n);
    count_deg_kernel<<<eb, 256>>>(ei, E);
    precompute_kernel<<<nb, 256>>>(n);
    partial_kernel<<<nb, 256>>>(n);
    scan_part_kernel<<<1, 512>>>(nb, n);
    rowptr_kernel<<<nb, 256>>>(n);
    fill_kernel<<<eb, 256>>>(ei, E);
    agg1_kernel<<<wb, 256>>>(feat, out, n);
    mma_gemm1<<<mb, 256, SMEM_G1>>>(W1, b1, out, n);
    sgather_kernel<<<wb, 256>>>(out, n);
    mma_gemm2<<<mb, 256, SMEM_G2>>>(Wl, bl, Wr, out, n);
}

// round 10
// speedup vs baseline: 2.9531x; 1.0496x over previous
#include <cuda_runtime.h>
#include <cuda_fp16.h>
#include <cstdint>

#define MAX_N 100352
#define MAX_E 1700000
#define MAX_PART 512
#define DIM 128

// ---------------- small device-global scratch (~8.4 MB) ----------------
__device__ int   g_deg[MAX_N];        // degree, then CSR fill cursor
__device__ float g_dinv[MAX_N];
__device__ float g_invcnt[MAX_N];
__device__ int   g_row[MAX_N + 1];
__device__ int   g_col[MAX_E];
__device__ int   g_part[MAX_PART];
__device__ int   g_idx64;

// ---------------- edge-index dtype detection ----------------
__global__ void detect_kernel(const int* ei32, long long words) {
    __shared__ int s;
    if (threadIdx.x == 0) s = 1;
    __syncthreads();
    long long limit = words < 8192 ? words : 8192;
    for (long long j = 1 + 2LL * threadIdx.x; j < limit; j += 2LL * blockDim.x)
        if (ei32[j] != 0) s = 0;
    __syncthreads();
    if (threadIdx.x == 0 && words > 0) g_idx64 = s;
}

__device__ __forceinline__ void load_edge(const void* ei, long long E, long long e,
                                          int& src, int& dst) {
    if (g_idx64) {
        const long long* p = (const long long*)ei;
        src = (int)p[e]; dst = (int)p[E + e];
    } else {
        const int* p = (const int*)ei;
        src = p[e]; dst = p[E + e];
    }
}

// ---------------- feat fp32 -> fp16 (slot high half of d_out); zero g_deg ----------------
__global__ __launch_bounds__(256) void conv_kernel(
    const float* __restrict__ feat, float* __restrict__ out, int n)
{
    int total = n * 32;   // float4 groups
    for (int idx = blockIdx.x * 256 + threadIdx.x; idx < total; idx += gridDim.x * 256) {
        int row = idx >> 5, q = idx & 31;
        float4 v = ((const float4*)feat)[idx];
        __half2* dst = (__half2*)((__half*)(out + (size_t)row * DIM + 64)) + q * 2;
        dst[0] = __floats2half2_rn(v.x, v.y);
        dst[1] = __floats2half2_rn(v.z, v.w);
    }
    for (int i = blockIdx.x * 256 + threadIdx.x; i < n; i += gridDim.x * 256)
        g_deg[i] = 0;
}

// ---------------- degree count ----------------
__global__ void count_deg_kernel(const void* ei, long long E) {
    long long e = (long long)blockIdx.x * blockDim.x + threadIdx.x;
    if (e < E) {
        int s, d; load_edge(ei, E, e, s, d);
        atomicAdd(&g_deg[d], 1);
    }
}

// ---------------- precompute norms + scan partials (fused) ----------------
__global__ __launch_bounds__(256) void precomp_partial_kernel(int n) {
    __shared__ int red[256];
    int i = blockIdx.x * 256 + threadIdx.x;
    int d = 0;
    if (i < n) {
        d = g_deg[i];
        g_dinv[i]   = rsqrtf((float)d + 1.0f);
        g_invcnt[i] = 1.0f / (float)(d > 0 ? d : 1);
    }
    red[threadIdx.x] = d;
    __syncthreads();
    for (int s = 128; s > 0; s >>= 1) {
        if (threadIdx.x < s) red[threadIdx.x] += red[threadIdx.x + s];
        __syncthreads();
    }
    if (threadIdx.x == 0) g_part[blockIdx.x] = red[0];
}

__global__ __launch_bounds__(512) void scan_part_kernel(int nb, int n) {
    __shared__ int sp[512];
    int t = threadIdx.x;
    int v = (t < nb) ? g_part[t] : 0;
    sp[t] = v;
    __syncthreads();
    for (int d = 1; d < 512; d <<= 1) {
        int u = (t >= d) ? sp[t - d] : 0;
        __syncthreads();
        sp[t] += u;
        __syncthreads();
    }
    if (t < nb) g_part[t] = sp[t] - v;
    if (t == 511) g_row[n] = sp[511];
}

__global__ __launch_bounds__(256) void rowptr_kernel(int n) {
    __shared__ int sp[256];
    int t = threadIdx.x;
    int i = blockIdx.x * 256 + t;
    int v = (i < n) ? g_deg[i] : 0;
    sp[t] = v;
    __syncthreads();
    for (int d = 1; d < 256; d <<= 1) {
        int u = (t >= d) ? sp[t - d] : 0;
        __syncthreads();
        sp[t] += u;
        __syncthreads();
    }
    int excl = sp[t] - v + g_part[blockIdx.x];
    if (i < n) { g_row[i] = excl; g_deg[i] = excl; }
}

__global__ void fill_kernel(const void* ei, long long E) {
    long long e = (long long)blockIdx.x * blockDim.x + threadIdx.x;
    if (e < E) {
        int s, d; load_edge(ei, E, e, s, d);
        int pos = atomicAdd(&g_deg[d], 1);
        g_col[pos] = s;
    }
}

// ---------------- L1 aggregate: fp16 feat gather (slot high) -> fp16 agg (slot low) ----------------
// warp per node; lane covers 4 halves. Reads slot-high bytes, writes slot-low
// bytes -> globally disjoint, race-free.
__global__ __launch_bounds__(256) void agg1_kernel(float* __restrict__ out, int n) {
    int node = blockIdx.x * 8 + (threadIdx.x >> 5);
    if (node >= n) return;
    const int lane = threadIdx.x & 31;
    const float di = g_dinv[node];

    const __half2* selfp = (const __half2*)((const __half*)(out + (size_t)node * DIM + 64)) + lane * 2;
    float2 f0 = __half22float2(selfp[0]);
    float2 f1 = __half22float2(selfp[1]);
    float c0 = di * di;
    float4 acc = make_float4(c0 * f0.x, c0 * f0.y, c0 * f1.x, c0 * f1.y);

    int p = g_row[node];
    const int pend = g_row[node + 1];
    for (; p + 2 <= pend; p += 2) {
        int j0 = g_col[p], j1 = g_col[p + 1];
        float ca = di * g_dinv[j0], cb = di * g_dinv[j1];
        const __half2* va = (const __half2*)((const __half*)(out + (size_t)j0 * DIM + 64)) + lane * 2;
        const __half2* vb = (const __half2*)((const __half*)(out + (size_t)j1 * DIM + 64)) + lane * 2;
        __half2 a0 = va[0], a1 = va[1], b0 = vb[0], b1 = vb[1];
        float2 fa0 = __half22float2(a0), fa1 = __half22float2(a1);
        float2 fb0 = __half22float2(b0), fb1 = __half22float2(b1);
        acc.x += ca * fa0.x + cb * fb0.x;
        acc.y += ca * fa0.y + cb * fb0.y;
        acc.z += ca * fa1.x + cb * fb1.x;
        acc.w += ca * fa1.y + cb * fb1.y;
    }
    if (p < pend) {
        int j = g_col[p];
        float c = di * g_dinv[j];
        const __half2* v = (const __half2*)((const __half*)(out + (size_t)j * DIM + 64)) + lane * 2;
        float2 fa = __half22float2(v[0]), fb = __half22float2(v[1]);
        acc.x += c * fa.x; acc.y += c * fa.y; acc.z += c * fb.x; acc.w += c * fb.y;
    }
    __half2* dst = (__half2*)(out + (size_t)node * DIM) + lane * 2;
    dst[0] = __floats2half2_rn(acc.x, acc.y);
    dst[1] = __floats2half2_rn(acc.z, acc.w);
}

// ---------------- tensor-core mma helper ----------------
__device__ __forceinline__ void mma16816(float* c, uint32_t a0, uint32_t a1,
                                         uint32_t a2, uint32_t a3,
                                         uint32_t b0, uint32_t b1) {
    asm volatile(
        "mma.sync.aligned.m16n8k16.row.col.f32.f16.f16.f32 "
        "{%0,%1,%2,%3}, {%4,%5,%6,%7}, {%8,%9}, {%0,%1,%2,%3};"
        : "+f"(c[0]), "+f"(c[1]), "+f"(c[2]), "+f"(c[3])
        : "r"(a0), "r"(a1), "r"(a2), "r"(a3), "r"(b0), "r"(b1));
}

// ---------------- GEMM1 (tc): X = relu(agg@W1^T + b1); agg fp16 slot low -> X fp16 slot low ----------------
__global__ __launch_bounds__(256) void mma_gemm1(
    const float* __restrict__ W1, const float* __restrict__ b1,
    float* __restrict__ out, int n)
{
    const int KP = 136;
    extern __shared__ __half sh[];
    __half* As = sh;                          // [128][136]
    __half* Bs = sh + 128 * KP;               // [128][136]
    float* bias_s = (float*)(Bs + 128 * KP);
    const int tid = threadIdx.x;
    const int block_row = blockIdx.x * 128;

    for (int i = tid; i < 128 * 32; i += 256) {
        int r = i >> 5, q = i & 31;
        float4 w = ((const float4*)W1)[i];
        __half2* dst = (__half2*)&Bs[r * KP + q * 4];
        dst[0] = __floats2half2_rn(w.x, w.y);
        dst[1] = __floats2half2_rn(w.z, w.w);
    }
    // A: straight fp16 copy of slot-low (agg) rows, 16 uint4 per row
    for (int i = tid; i < 128 * 16; i += 256) {
        int r = i >> 4, q = i & 15;
        int gr = block_row + r;
        uint4 v = make_uint4(0, 0, 0, 0);
        if (gr < n) v = ((const uint4*)(out + (size_t)gr * DIM))[q];
        *(uint4*)&As[r * KP + q * 8] = v;
    }
    if (tid < 128) bias_s[tid] = b1[tid];
    __syncthreads();

    const int warp = tid >> 5, lane = tid & 31;
    const int m0 = warp * 16;
    const int r = lane >> 2, c2 = (lane & 3) * 2;

    float acc[16][4];
    #pragma unroll
    for (int t = 0; t < 16; t++)
        #pragma unroll
        for (int q = 0; q < 4; q++) acc[t][q] = 0.f;

    #pragma unroll
    for (int kk = 0; kk < 128; kk += 16) {
        uint32_t a0 = *(const uint32_t*)&As[(m0 + r) * KP + kk + c2];
        uint32_t a1 = *(const uint32_t*)&As[(m0 + r + 8) * KP + kk + c2];
        uint32_t a2 = *(const uint32_t*)&As[(m0 + r) * KP + kk + 8 + c2];
        uint32_t a3 = *(const uint32_t*)&As[(m0 + r + 8) * KP + kk + 8 + c2];
        #pragma unroll
        for (int nt = 0; nt < 16; nt++) {
            uint32_t b0 = *(const uint32_t*)&Bs[(nt * 8 + r) * KP + kk + c2];
            uint32_t b1r = *(const uint32_t*)&Bs[(nt * 8 + r) * KP + kk + 8 + c2];
            mma16816(acc[nt], a0, a1, a2, a3, b0, b1r);
        }
    }

    const int row0 = block_row + m0 + r;
    #pragma unroll
    for (int nt = 0; nt < 16; nt++) {
        int col = nt * 8 + c2;
        float bx = bias_s[col], by = bias_s[col + 1];
        if (row0 < n) {
            __half2 h = __floats2half2_rn(fmaxf(acc[nt][0] + bx, 0.f),
                                          fmaxf(acc[nt][1] + by, 0.f));
            *(__half2*)((__half*)(out + (size_t)row0 * DIM) + col) = h;
        }
        if (row0 + 8 < n) {
            __half2 h = __floats2half2_rn(fmaxf(acc[nt][2] + bx, 0.f),
                                          fmaxf(acc[nt][3] + by, 0.f));
            *(__half2*)((__half*)(out + (size_t)(row0 + 8) * DIM) + col) = h;
        }
    }
}

// ---------------- SAGE sum: S_i = sum_j X_j (fp32 acc) -> fp16 slot high ----------------
__global__ __launch_bounds__(256) void sgather_kernel(float* __restrict__ out, int n) {
    int node = blockIdx.x * 8 + (threadIdx.x >> 5);
    if (node >= n) return;
    const int lane = threadIdx.x & 31;

    float4 acc = make_float4(0.f, 0.f, 0.f, 0.f);
    int p = g_row[node];
    const int pend = g_row[node + 1];
    for (; p + 2 <= pend; p += 2) {
        int j0 = g_col[p], j1 = g_col[p + 1];
        const __half2* va = (const __half2*)(out + (size_t)j0 * DIM) + lane * 2;
        const __half2* vb = (const __half2*)(out + (size_t)j1 * DIM) + lane * 2;
        __half2 a0 = va[0], a1 = va[1], b0 = vb[0], b1 = vb[1];
        float2 fa0 = __half22float2(a0), fa1 = __half22float2(a1);
        float2 fb0 = __half22float2(b0), fb1 = __half22float2(b1);
        acc.x += fa0.x + fb0.x; acc.y += fa0.y + fb0.y;
        acc.z += fa1.x + fb1.x; acc.w += fa1.y + fb1.y;
    }
    if (p < pend) {
        int j = g_col[p];
        const __half2* v = (const __half2*)(out + (size_t)j * DIM) + lane * 2;
        float2 fa = __half22float2(v[0]), fb = __half22float2(v[1]);
        acc.x += fa.x; acc.y += fa.y; acc.z += fb.x; acc.w += fb.y;
    }
    __half2* shp = (__half2*)((__half*)(out + (size_t)node * DIM + 64)) + lane * 2;
    shp[0] = __floats2half2_rn(acc.x, acc.y);
    shp[1] = __floats2half2_rn(acc.z, acc.w);
}

// ---------------- GEMM2 (tc): out = relu([S*invcnt | X] @ [Wl|Wr]^T + bl) ----------------
__global__ __launch_bounds__(256) void mma_gemm2(
    const float* __restrict__ Wl, const float* __restrict__ bl,
    const float* __restrict__ Wr, float* __restrict__ out, int n)
{
    const int KP = 264;
    extern __shared__ __half sh[];
    __half* As = sh;                          // [128][264]
    __half* Bs = sh + 128 * KP;               // [128][264]
    float* bias_s = (float*)(Bs + 128 * KP);
    const int tid = threadIdx.x;
    const int block_row = blockIdx.x * 128;

    for (int i = tid; i < 128 * 32; i += 256) {
        int r = i >> 5, q = i & 31;
        float4 w = ((const float4*)Wl)[i];
        __half2* dst = (__half2*)&Bs[r * KP + q * 4];
        dst[0] = __floats2half2_rn(w.x, w.y);
        dst[1] = __floats2half2_rn(w.z, w.w);
    }
    for (int i = tid; i < 128 * 32; i += 256) {
        int r = i >> 5, q = i & 31;
        float4 w = ((const float4*)Wr)[i];
        __half2* dst = (__half2*)&Bs[r * KP + 128 + q * 4];
        dst[0] = __floats2half2_rn(w.x, w.y);
        dst[1] = __floats2half2_rn(w.z, w.w);
    }
    for (int i = tid; i < 128 * 64; i += 256) {
        int row = i >> 6, q = i & 63;
        int gr = block_row + row;
        __half2 xh = __float2half2_rn(0.f), shv = __float2half2_rn(0.f);
        if (gr < n) {
            const __half2* slot = (const __half2*)(out + (size_t)gr * DIM);
            xh = slot[q];
            __half2 sr = slot[64 + q];
            float ic = g_invcnt[gr];
            float2 sf = __half22float2(sr);
            shv = __floats2half2_rn(sf.x * ic, sf.y * ic);
        }
        ((__half2*)&As[row * KP])[q] = shv;
        ((__half2*)&As[row * KP + 128])[q] = xh;
    }
    if (tid < 128) bias_s[tid] = bl[tid];
    __syncthreads();

    const int warp = tid >> 5, lane = tid & 31;
    const int m0 = warp * 16;
    const int r = lane >> 2, c2 = (lane & 3) * 2;

    float acc[16][4];
    #pragma unroll
    for (int t = 0; t < 16; t++)
        #pragma unroll
        for (int q = 0; q < 4; q++) acc[t][q] = 0.f;

    #pragma unroll
    for (int kk = 0; kk < 256; kk += 16) {
        uint32_t a0 = *(const uint32_t*)&As[(m0 + r) * KP + kk + c2];
        uint32_t a1 = *(const uint32_t*)&As[(m0 + r + 8) * KP + kk + c2];
        uint32_t a2 = *(const uint32_t*)&As[(m0 + r) * KP + kk + 8 + c2];
        uint32_t a3 = *(const uint32_t*)&As[(m0 + r + 8) * KP + kk + 8 + c2];
        #pragma unroll
        for (int nt = 0; nt < 16; nt++) {
            uint32_t b0 = *(const uint32_t*)&Bs[(nt * 8 + r) * KP + kk + c2];
            uint32_t b1r = *(const uint32_t*)&Bs[(nt * 8 + r) * KP + kk + 8 + c2];
            mma16816(acc[nt], a0, a1, a2, a3, b0, b1r);
        }
    }

    const int row0 = block_row + m0 + r;
    #pragma unroll
    for (int nt = 0; nt < 16; nt++) {
        int col = nt * 8 + c2;
        float bx = bias_s[col], by = bias_s[col + 1];
        if (row0 < n) {
            float2 o = make_float2(fmaxf(acc[nt][0] + bx, 0.f),
                                   fmaxf(acc[nt][1] + by, 0.f));
            *(float2*)(out + (size_t)row0 * DIM + col) = o;
        }
        if (row0 + 8 < n) {
            float2 o = make_float2(fmaxf(acc[nt][2] + bx, 0.f),
                                   fmaxf(acc[nt][3] + by, 0.f));
            *(float2*)(out + (size_t)(row0 + 8) * DIM + col) = o;
        }
    }
}

static const int SMEM_G1 = (128 * 136 * 2) * 2 + 512;   // ~70 KB
static const int SMEM_G2 = (128 * 264 * 2) * 2 + 512;   // ~136 KB

// ---------------- host launcher ----------------
extern "C" void kernel_launch(void* const* d_in, const int* in_sizes, int n_in,
                              void* d_out, int out_size) {
    const float* feat = (const float*)d_in[0];
    const void*  ei   = d_in[1];
    const float* W1   = (const float*)d_in[2];
    const float* b1   = (const float*)d_in[3];
    const float* Wl   = (const float*)d_in[4];
    const float* bl   = (const float*)d_in[5];
    const float* Wr   = (const float*)d_in[6];
    float* out = (float*)d_out;

    const int n = in_sizes[0] / DIM;
    const long long E = (long long)in_sizes[1] / 2;

    static bool attr_done = false;
    if (!attr_done) {
        cudaFuncSetAttribute(mma_gemm1, cudaFuncAttributeMaxDynamicSharedMemorySize, SMEM_G1);
        cudaFuncSetAttribute(mma_gemm2, cudaFuncAttributeMaxDynamicSharedMemorySize, SMEM_G2);
        attr_done = true;
    }

    const int eb = (int)((E + 255) / 256);
    const int nb = (n + 255) / 256;          // scan partial count
    const int wb = (n + 7) / 8;
    const int mb = (n + 127) / 128;
    const int cb = (n * 32 + 255) / 256;

    detect_kernel<<<1, 256>>>((const int*)ei, 2 * E);
    conv_kernel<<<cb, 256>>>(feat, out, n);              // feat16 -> slot high; deg=0
    count_deg_kernel<<<eb, 256>>>(ei, E);
    precomp_partial_kernel<<<nb, 256>>>(n);              // dinv/invcnt + partials
    scan_part_kernel<<<1, 512>>>(nb, n);
    rowptr_kernel<<<nb, 256>>>(n);
    fill_kernel<<<eb, 256>>>(ei, E);
    agg1_kernel<<<wb, 256>>>(out, n);                    // feat16 gather -> agg16 slot low
    mma_gemm1<<<mb, 256, SMEM_G1>>>(W1, b1, out, n);     // X16 -> slot low
    sgather_kernel<<<wb, 256>>>(out, n);                 // S16 -> slot high
    mma_gemm2<<<mb, 256, SMEM_G2>>>(Wl, bl, Wr, out, n); // fp32 out
}